// round 2
// baseline (speedup 1.0000x reference)
#include <cuda_runtime.h>
#include <cuda_bf16.h>

// Problem constants (fixed shapes)
#define NN     10000
#define NS     64
#define NV     64
#define HID    128
#define WN     320
#define KS0    192
#define EAD    20
#define TPS    128
#define TPV    192

#define TE     16      // edges per block
#define BT     256     // threads per block

#define INV_SQRT3 0.5773502691896258f
#define INV_SQRT2 0.7071067811865476f

typedef unsigned long long u64;

__device__ float g_sp[NN * NS];        // silu(xs @ W_pre_s + b)
__device__ float g_vp[NN * 3 * NV];    // gated vectors, layout [n][c*64+v]

__device__ __forceinline__ float siluf(float x) { return x / (1.0f + __expf(-x)); }

__device__ __forceinline__ void fma2(u64& d, u64 a, u64 b) {
    asm("fma.rn.f32x2 %0, %1, %2, %0;" : "+l"(d) : "l"(a), "l"(b));
}
__device__ __forceinline__ u64 pk(float x, float y) {
    u64 r; asm("mov.b64 %0, {%1, %2};" : "=l"(r) : "f"(x), "f"(y)); return r;
}
__device__ __forceinline__ float2 up(u64 a) {
    float2 r; asm("mov.b64 {%0, %1}, %2;" : "=f"(r.x), "=f"(r.y) : "l"(a)); return r;
}

// ---------------------------------------------------------------------------
// Kernel 1: per-node precompute of gated (s_p, v_p)
// ---------------------------------------------------------------------------
__global__ __launch_bounds__(256) void node_kernel(
    const float* __restrict__ x,
    const float* __restrict__ Wps, const float* __restrict__ bps,
    const float* __restrict__ Wpv,
    const float* __restrict__ gw, const float* __restrict__ gb,
    int N)
{
    __shared__ float sx[4][256];
    const int ln = threadIdx.x >> 6;
    const int v  = threadIdx.x & 63;
    const int n  = blockIdx.x * 4 + ln;

    if (n < N) {
        #pragma unroll
        for (int i = v; i < 256; i += 64) sx[ln][i] = x[n * 256 + i];
    }
    __syncthreads();
    if (n >= N) return;

    const float* xs = sx[ln];
    const float* xv = sx[ln] + 64;

    float sacc = bps[v];
    #pragma unroll 4
    for (int i = 0; i < NS; i++) sacc = fmaf(xs[i], Wps[i * NS + v], sacc);

    float ax = 0.f, ay = 0.f, az = 0.f;
    #pragma unroll 4
    for (int u = 0; u < NV; u++) {
        float w = Wpv[u * NV + v];
        ax = fmaf(xv[u * 3 + 0], w, ax);
        ay = fmaf(xv[u * 3 + 1], w, ay);
        az = fmaf(xv[u * 3 + 2], w, az);
    }
    float nrm = sqrtf(ax * ax + ay * ay + az * az + 1e-12f);
    float g = siluf(nrm * gw[v] + gb[v]);

    g_sp[n * NS + v] = siluf(sacc);
    g_vp[n * 192 + 0 * 64 + v] = ax * g;
    g_vp[n * 192 + 1 * 64 + v] = ay * g;
    g_vp[n * 192 + 2 * 64 + v] = az * g;
}

// ---------------------------------------------------------------------------
// Kernel 2: fused edge layer. All activations edge-minor [feat][16] in smem.
// smem map (floats):
//   region A (union, 9216):
//     s0t  @0     [192][16]   (dies after ph2)
//     h1t  @3072  [128][16]   (dies after ph3)
//     r1t  @5120  [128][16]   (dies after ph3)
//     Vt   @0     [192*3][16] (phases 4a..5b)
//   spsT  @9216   [128][16]   (src u 0..63 | dst u 64..127)
//   vpsT  @11264  [384][16]   (src j 0..191 | dst j 192..383), j = c*64+v
//   tpwT  @17408  [320][16]
//   outsT @22528  [128][16]
//   eat   @24576  [20][16]
//   sidx  @24896  32 ints
// ---------------------------------------------------------------------------
__global__ __launch_bounds__(BT, 2) void edge_kernel(
    const float* __restrict__ x,
    const float* __restrict__ edge_attr,
    const float* __restrict__ fij_in,
    const float* __restrict__ Ws1, const float* __restrict__ bs1,
    const float* __restrict__ Ws2, const float* __restrict__ bs2,
    const float* __restrict__ Wr1, const float* __restrict__ br1,
    const float* __restrict__ Wr2, const float* __restrict__ br2,
    const float* __restrict__ gwp, const float* __restrict__ gbp,
    const float* __restrict__ Wpost_s, const float* __restrict__ Wpost_v,
    const int* __restrict__ ei,
    float* __restrict__ out, int E)
{
    extern __shared__ float sm[];
    float* s0t   = sm;                 // 3072
    float* h1t   = sm + 3072;          // 2048
    float* r1t   = sm + 5120;          // 2048
    float* Vt    = sm;                 // 9216 (after ph3)
    float* spsT  = sm + 9216;          // 2048
    float* vpsT  = sm + 11264;         // 6144
    float* tpwT  = sm + 17408;         // 5120
    float* outsT = sm + 22528;         // 2048
    float* eat   = sm + 24576;         // 320
    int*   sidx  = (int*)(sm + 24896); // 32

    const int tid = threadIdx.x;
    const int e0  = blockIdx.x * TE;

    if (tid < TE) {
        sidx[tid]      = ei[e0 + tid];
        sidx[TE + tid] = ei[E + e0 + tid];
    }
    for (int idx = tid; idx < TE * EAD; idx += BT) {
        int e = idx & 15, i = idx >> 4;
        eat[i * 16 + e] = edge_attr[(size_t)(e0 + e) * EAD + i];
    }
    __syncthreads();

    // ---- Phase 1: s0t (transposed) + stage gated node features ----
    {
        const int e = tid & 15, q = tid >> 4;   // q = 0..15
        const int s = sidx[e], d = sidx[TE + e];
        const float* xs = x + (size_t)s * 256;
        const float* xd = x + (size_t)d * 256;

        float4 a = *(const float4*)(xs + q * 4);
        float4 b = *(const float4*)(xd + q * 4);
        s0t[(q*4+0)*16+e] = a.x; s0t[(q*4+1)*16+e] = a.y;
        s0t[(q*4+2)*16+e] = a.z; s0t[(q*4+3)*16+e] = a.w;
        s0t[(64+q*4+0)*16+e] = b.x; s0t[(64+q*4+1)*16+e] = b.y;
        s0t[(64+q*4+2)*16+e] = b.z; s0t[(64+q*4+3)*16+e] = b.w;

        float4 v0 = *(const float4*)(xs + 64 + q*12);
        float4 v1 = *(const float4*)(xs + 64 + q*12 + 4);
        float4 v2 = *(const float4*)(xs + 64 + q*12 + 8);
        float4 w0 = *(const float4*)(xd + 64 + q*12);
        float4 w1 = *(const float4*)(xd + 64 + q*12 + 4);
        float4 w2 = *(const float4*)(xd + 64 + q*12 + 8);
        float d0 = v0.x*w0.x + v0.y*w0.y + v0.z*w0.z;
        float d1 = v0.w*w0.w + v1.x*w1.x + v1.y*w1.y;
        float d2 = v1.z*w1.z + v1.w*w1.w + v2.x*w2.x;
        float d3 = v2.y*w2.y + v2.z*w2.z + v2.w*w2.w;
        s0t[(128+q*4+0)*16+e] = d0; s0t[(128+q*4+1)*16+e] = d1;
        s0t[(128+q*4+2)*16+e] = d2; s0t[(128+q*4+3)*16+e] = d3;

        // gated scalars
        float4 gs = *(const float4*)(g_sp + (size_t)s * 64 + q * 4);
        float4 gd = *(const float4*)(g_sp + (size_t)d * 64 + q * 4);
        spsT[(q*4+0)*16+e] = gs.x; spsT[(q*4+1)*16+e] = gs.y;
        spsT[(q*4+2)*16+e] = gs.z; spsT[(q*4+3)*16+e] = gs.w;
        spsT[(64+q*4+0)*16+e] = gd.x; spsT[(64+q*4+1)*16+e] = gd.y;
        spsT[(64+q*4+2)*16+e] = gd.z; spsT[(64+q*4+3)*16+e] = gd.w;

        // gated vectors: 12 floats/node/thread
        {
            float4 p0 = *(const float4*)(g_vp + (size_t)s * 192 + q * 12);
            float4 p1 = *(const float4*)(g_vp + (size_t)s * 192 + q * 12 + 4);
            float4 p2 = *(const float4*)(g_vp + (size_t)s * 192 + q * 12 + 8);
            float pv[12] = {p0.x,p0.y,p0.z,p0.w,p1.x,p1.y,p1.z,p1.w,p2.x,p2.y,p2.z,p2.w};
            #pragma unroll
            for (int r = 0; r < 12; r++) vpsT[(q*12 + r)*16 + e] = pv[r];
        }
        {
            float4 p0 = *(const float4*)(g_vp + (size_t)d * 192 + q * 12);
            float4 p1 = *(const float4*)(g_vp + (size_t)d * 192 + q * 12 + 4);
            float4 p2 = *(const float4*)(g_vp + (size_t)d * 192 + q * 12 + 8);
            float pv[12] = {p0.x,p0.y,p0.z,p0.w,p1.x,p1.y,p1.z,p1.w,p2.x,p2.y,p2.z,p2.w};
            #pragma unroll
            for (int r = 0; r < 12; r++) vpsT[(192 + q*12 + r)*16 + e] = pv[r];
        }
    }
    __syncthreads();

    // ---- Phase 2: h1 = silu(s0@Ws1+bs1), r1 = silu(ea@Wr1+br1) (f32x2) ----
    {
        const int k  = tid & 127;
        const int eo = tid >> 7;   // edges eo*8 .. eo*8+7
        {
            float bk = bs1[k];
            u64 a0 = pk(bk, bk), a1 = a0, a2 = a0, a3 = a0;
            #pragma unroll 4
            for (int i = 0; i < KS0; i++) {
                float w = Ws1[i * HID + k];
                u64 ww = pk(w, w);
                ulonglong2 s4 = *(const ulonglong2*)(s0t + i*16 + eo*8);
                ulonglong2 s5 = *(const ulonglong2*)(s0t + i*16 + eo*8 + 4);
                fma2(a0, s4.x, ww); fma2(a1, s4.y, ww);
                fma2(a2, s5.x, ww); fma2(a3, s5.y, ww);
            }
            float4 o0, o1; float2 p;
            p = up(a0); o0.x = siluf(p.x); o0.y = siluf(p.y);
            p = up(a1); o0.z = siluf(p.x); o0.w = siluf(p.y);
            p = up(a2); o1.x = siluf(p.x); o1.y = siluf(p.y);
            p = up(a3); o1.z = siluf(p.x); o1.w = siluf(p.y);
            *(float4*)(h1t + k*16 + eo*8)     = o0;
            *(float4*)(h1t + k*16 + eo*8 + 4) = o1;
        }
        {
            float bk = br1[k];
            u64 a0 = pk(bk, bk), a1 = a0, a2 = a0, a3 = a0;
            #pragma unroll
            for (int i = 0; i < EAD; i++) {
                float w = Wr1[i * HID + k];
                u64 ww = pk(w, w);
                ulonglong2 s4 = *(const ulonglong2*)(eat + i*16 + eo*8);
                ulonglong2 s5 = *(const ulonglong2*)(eat + i*16 + eo*8 + 4);
                fma2(a0, s4.x, ww); fma2(a1, s4.y, ww);
                fma2(a2, s5.x, ww); fma2(a3, s5.y, ww);
            }
            float4 o0, o1; float2 p;
            p = up(a0); o0.x = siluf(p.x); o0.y = siluf(p.y);
            p = up(a1); o0.z = siluf(p.x); o0.w = siluf(p.y);
            p = up(a2); o1.x = siluf(p.x); o1.y = siluf(p.y);
            p = up(a3); o1.z = siluf(p.x); o1.w = siluf(p.y);
            *(float4*)(r1t + k*16 + eo*8)     = o0;
            *(float4*)(r1t + k*16 + eo*8 + 4) = o1;
        }
    }
    __syncthreads();

    // ---- Phase 3: tp_w = (h1@Ws2+bs2)*(r1@Wr2+br2) (f32x2, all 16 edges/thread) ----
    #pragma unroll
    for (int pass = 0; pass < 2; pass++) {
        int kv = tid + pass * 256;
        if (kv < WN) {
            u64 at[8], ar[8];
            #pragma unroll
            for (int g = 0; g < 8; g++) { at[g] = pk(0.f, 0.f); ar[g] = at[g]; }
            #pragma unroll 2
            for (int i = 0; i < HID; i++) {
                float wts = Ws2[i * WN + kv];
                float wrs = Wr2[i * WN + kv];
                u64 wt = pk(wts, wts), wr = pk(wrs, wrs);
                #pragma unroll
                for (int g = 0; g < 4; g++) {
                    ulonglong2 h = *(const ulonglong2*)(h1t + i*16 + g*4);
                    fma2(at[2*g],   h.x, wt);
                    fma2(at[2*g+1], h.y, wt);
                }
                #pragma unroll
                for (int g = 0; g < 4; g++) {
                    ulonglong2 r = *(const ulonglong2*)(r1t + i*16 + g*4);
                    fma2(ar[2*g],   r.x, wr);
                    fma2(ar[2*g+1], r.y, wr);
                }
            }
            float b2 = bs2[kv], c2 = br2[kv];
            #pragma unroll
            for (int g = 0; g < 4; g++) {
                float2 t0 = up(at[2*g]), t1 = up(at[2*g+1]);
                float2 r0 = up(ar[2*g]), r1v = up(ar[2*g+1]);
                float4 o;
                o.x = (t0.x + b2) * (r0.x + c2);
                o.y = (t0.y + b2) * (r0.y + c2);
                o.z = (t1.x + b2) * (r1v.x + c2);
                o.w = (t1.y + b2) * (r1v.y + c2);
                *(float4*)(tpwT + kv*16 + g*4) = o;
            }
        }
    }
    __syncthreads();

    // ---- Phase 4a: out_v gated -> Vt[u][c][e] (overlays s0t/h1t/r1t) ----
    #pragma unroll
    for (int it = 0; it < 12; it++) {
        int idx = tid + it * 256;     // 3072 = 16 * 192
        int e = idx & 15, u = idx >> 4;
        float vx, vy, vz;
        if (u < 64) {
            float coef = tpwT[(64+u)*16+e] * spsT[u*16+e];
            vx = coef * vpsT[(192 +       u)*16+e];
            vy = coef * vpsT[(192 + 64  + u)*16+e];
            vz = coef * vpsT[(192 + 128 + u)*16+e];
        } else if (u < 128) {
            int uu = u - 64;
            float coef = tpwT[(128+uu)*16+e] * spsT[(64+uu)*16+e];
            vx = coef * vpsT[(      uu)*16+e];
            vy = coef * vpsT[( 64 + uu)*16+e];
            vz = coef * vpsT[(128 + uu)*16+e];
        } else {
            int uu = u - 128;
            float w5 = tpwT[(256+uu)*16+e] * INV_SQRT2;
            float ax = vpsT[uu*16+e],        ay = vpsT[(64+uu)*16+e],  az = vpsT[(128+uu)*16+e];
            float bx = vpsT[(192+uu)*16+e],  by = vpsT[(256+uu)*16+e], bz = vpsT[(320+uu)*16+e];
            vx = w5 * (ay*bz - az*by);
            vy = w5 * (az*bx - ax*bz);
            vz = w5 * (ax*by - ay*bx);
        }
        float nrm = sqrtf(vx*vx + vy*vy + vz*vz + 1e-12f);
        float g = siluf(nrm * gwp[u] + gbp[u]);
        Vt[(u*3+0)*16+e] = vx * g;
        Vt[(u*3+1)*16+e] = vy * g;
        Vt[(u*3+2)*16+e] = vz * g;
    }

    // ---- Phase 4b: out_s -> outsT[j][e] ----
    #pragma unroll
    for (int it = 0; it < 8; it++) {
        int idx = tid + it * 256;     // 2048 = 16 * 128
        int e = idx & 15, j = idx >> 4;
        float val;
        if (j < 64) {
            val = tpwT[j*16+e] * spsT[j*16+e] * spsT[(64+j)*16+e];
        } else {
            int u = j - 64;
            float dt = vpsT[u*16+e]       * vpsT[(192+u)*16+e]
                     + vpsT[(64+u)*16+e]  * vpsT[(256+u)*16+e]
                     + vpsT[(128+u)*16+e] * vpsT[(320+u)*16+e];
            val = tpwT[(192+u)*16+e] * dt * INV_SQRT3;
        }
        outsT[j*16+e] = siluf(val);
    }
    __syncthreads();

    // ---- Phase 5a: fij_s = out_s @ W_post_s + fij_in ----
    {
        const int v  = tid & 63;
        const int eo = tid >> 6;        // 4 edges: eo*4 .. eo*4+3
        u64 a0 = pk(0.f, 0.f), a1 = a0;
        #pragma unroll 4
        for (int j = 0; j < TPS; j++) {
            float w = Wpost_s[j * NS + v];
            u64 ww = pk(w, w);
            ulonglong2 o = *(const ulonglong2*)(outsT + j*16 + eo*4);
            fma2(a0, o.x, ww); fma2(a1, o.y, ww);
        }
        float2 p0 = up(a0), p1 = up(a1);
        float vals[4] = {p0.x, p0.y, p1.x, p1.y};
        #pragma unroll
        for (int t = 0; t < 4; t++) {
            size_t o = (size_t)(e0 + eo*4 + t) * 256 + v;
            out[o] = fij_in[o] + vals[t];
        }
    }

    // ---- Phase 5b: fij_v = out_v @ W_post_v + fij_in ----
    {
        const int v = tid & 63;
        const int g = tid >> 6;         // 4 edges: g*4 .. g*4+3
        u64 b[6];
        #pragma unroll
        for (int p = 0; p < 6; p++) b[p] = pk(0.f, 0.f);
        #pragma unroll 2
        for (int u = 0; u < TPV; u++) {
            float w = Wpost_v[u * NV + v];
            u64 ww = pk(w, w);
            #pragma unroll
            for (int c = 0; c < 3; c++) {
                ulonglong2 ov = *(const ulonglong2*)(Vt + (u*3+c)*16 + g*4);
                fma2(b[c*2],   ov.x, ww);
                fma2(b[c*2+1], ov.y, ww);
            }
        }
        #pragma unroll
        for (int c = 0; c < 3; c++) {
            float2 q0 = up(b[c*2]), q1 = up(b[c*2+1]);
            float vals[4] = {q0.x, q0.y, q1.x, q1.y};
            #pragma unroll
            for (int t = 0; t < 4; t++) {
                size_t o = (size_t)(e0 + g*4 + t) * 256 + 64 + (size_t)v*3 + c;
                out[o] = fij_in[o] + vals[t];
            }
        }
    }
}

// ---------------------------------------------------------------------------
extern "C" void kernel_launch(void* const* d_in, const int* in_sizes, int n_in,
                              void* d_out, int out_size)
{
    const float* x         = (const float*)d_in[0];
    const float* edge_attr = (const float*)d_in[1];
    const float* fij_in    = (const float*)d_in[2];
    const float* W_pre_s   = (const float*)d_in[3];
    const float* b_pre_s   = (const float*)d_in[4];
    const float* W_pre_v   = (const float*)d_in[5];
    const float* gw_pre    = (const float*)d_in[6];
    const float* gb_pre    = (const float*)d_in[7];
    const float* Ws1       = (const float*)d_in[8];
    const float* bs1       = (const float*)d_in[9];
    const float* Ws2       = (const float*)d_in[10];
    const float* bs2       = (const float*)d_in[11];
    const float* Wr1       = (const float*)d_in[12];
    const float* br1       = (const float*)d_in[13];
    const float* Wr2       = (const float*)d_in[14];
    const float* br2       = (const float*)d_in[15];
    const float* gw_post   = (const float*)d_in[16];
    const float* gb_post   = (const float*)d_in[17];
    const float* W_post_s  = (const float*)d_in[18];
    const float* W_post_v  = (const float*)d_in[19];
    const int*   ei        = (const int*)d_in[20];

    const int N = in_sizes[0] / 256;
    const int E = in_sizes[2] / 256;

    node_kernel<<<(N + 3) / 4, 256>>>(x, W_pre_s, b_pre_s, W_pre_v, gw_pre, gb_pre, N);

    const size_t shm = (size_t)24928 * 4;   // 99712 B
    cudaFuncSetAttribute(edge_kernel, cudaFuncAttributeMaxDynamicSharedMemorySize, (int)shm);

    edge_kernel<<<E / TE, BT, shm>>>(
        x, edge_attr, fij_in,
        Ws1, bs1, Ws2, bs2, Wr1, br1, Wr2, br2,
        gw_post, gb_post, W_post_s, W_post_v,
        ei, (float*)d_out, E);
}

// round 3
// speedup vs baseline: 1.0926x; 1.0926x over previous
#include <cuda_runtime.h>
#include <cuda_bf16.h>

// Problem constants (fixed shapes)
#define NN     10000
#define NS     64
#define NV     64
#define HID    128
#define WN     320
#define KS0    192
#define EAD    20
#define TPS    128
#define TPV    192

#define TE     16      // edges per block
#define BT     256     // threads per block

#define INV_SQRT3 0.5773502691896258f
#define INV_SQRT2 0.7071067811865476f

typedef unsigned long long u64;

__device__ float g_sp[NN * NS];        // silu(xs @ W_pre_s + b)
__device__ float g_vp[NN * 3 * NV];    // gated vectors, layout [n][c*64+v]

__device__ __forceinline__ float siluf(float x) { return x / (1.0f + __expf(-x)); }

__device__ __forceinline__ void fma2(u64& d, u64 a, u64 b) {
    asm("fma.rn.f32x2 %0, %1, %2, %0;" : "+l"(d) : "l"(a), "l"(b));
}
__device__ __forceinline__ u64 pk(float x, float y) {
    u64 r; asm("mov.b64 %0, {%1, %2};" : "=l"(r) : "f"(x), "f"(y)); return r;
}
__device__ __forceinline__ float2 up(u64 a) {
    float2 r; asm("mov.b64 {%0, %1}, %2;" : "=f"(r.x), "=f"(r.y) : "l"(a)); return r;
}

// ---------------------------------------------------------------------------
// Kernel 1: per-node precompute of gated (s_p, v_p)
// ---------------------------------------------------------------------------
__global__ __launch_bounds__(256) void node_kernel(
    const float* __restrict__ x,
    const float* __restrict__ Wps, const float* __restrict__ bps,
    const float* __restrict__ Wpv,
    const float* __restrict__ gw, const float* __restrict__ gb,
    int N)
{
    __shared__ float sx[4][256];
    const int ln = threadIdx.x >> 6;
    const int v  = threadIdx.x & 63;
    const int n  = blockIdx.x * 4 + ln;

    if (n < N) {
        #pragma unroll
        for (int i = v; i < 256; i += 64) sx[ln][i] = x[n * 256 + i];
    }
    __syncthreads();
    if (n >= N) return;

    const float* xs = sx[ln];
    const float* xv = sx[ln] + 64;

    float sacc = bps[v];
    #pragma unroll 4
    for (int i = 0; i < NS; i++) sacc = fmaf(xs[i], Wps[i * NS + v], sacc);

    float ax = 0.f, ay = 0.f, az = 0.f;
    #pragma unroll 4
    for (int u = 0; u < NV; u++) {
        float w = Wpv[u * NV + v];
        ax = fmaf(xv[u * 3 + 0], w, ax);
        ay = fmaf(xv[u * 3 + 1], w, ay);
        az = fmaf(xv[u * 3 + 2], w, az);
    }
    float nrm = sqrtf(ax * ax + ay * ay + az * az + 1e-12f);
    float g = siluf(nrm * gw[v] + gb[v]);

    g_sp[n * NS + v] = siluf(sacc);
    g_vp[n * 192 + 0 * 64 + v] = ax * g;
    g_vp[n * 192 + 1 * 64 + v] = ay * g;
    g_vp[n * 192 + 2 * 64 + v] = az * g;
}

// ---------------------------------------------------------------------------
// Kernel 2: fused edge layer.
// GEMM phases use warp-homogeneous activation addresses -> LDS broadcasts.
// smem map (floats):
//   s0t  @0     [192][16]   (dies after ph2)
//   h1t  @3072  [128][16]   (dies after ph3)
//   r1t  @5120  [128][16]   (dies after ph3)
//   Vt   @0     [192][48]   rows u: 3c*16e contiguous (phases 4a..5b)
//   spsT @9216  [128][16]
//   vpsT @11264 [384][16]
//   tpwT @17408 [320][16]
//   outsT@22528 [128][16]
//   eat  @24576 [20][16]
//   sidx @24896 32 ints
// ---------------------------------------------------------------------------
__global__ __launch_bounds__(BT, 2) void edge_kernel(
    const float* __restrict__ x,
    const float* __restrict__ edge_attr,
    const float* __restrict__ fij_in,
    const float* __restrict__ Ws1, const float* __restrict__ bs1,
    const float* __restrict__ Ws2, const float* __restrict__ bs2,
    const float* __restrict__ Wr1, const float* __restrict__ br1,
    const float* __restrict__ Wr2, const float* __restrict__ br2,
    const float* __restrict__ gwp, const float* __restrict__ gbp,
    const float* __restrict__ Wpost_s, const float* __restrict__ Wpost_v,
    const int* __restrict__ ei,
    float* __restrict__ out, int E)
{
    extern __shared__ float sm[];
    float* s0t   = sm;                 // 3072
    float* h1t   = sm + 3072;          // 2048
    float* r1t   = sm + 5120;          // 2048
    float* Vt    = sm;                 // 9216 (after ph3)
    float* spsT  = sm + 9216;          // 2048
    float* vpsT  = sm + 11264;         // 6144
    float* tpwT  = sm + 17408;         // 5120
    float* outsT = sm + 22528;         // 2048
    float* eat   = sm + 24576;         // 320
    int*   sidx  = (int*)(sm + 24896); // 32

    const int tid = threadIdx.x;
    const int e0  = blockIdx.x * TE;

    if (tid < TE) {
        sidx[tid]      = ei[e0 + tid];
        sidx[TE + tid] = ei[E + e0 + tid];
    }
    for (int idx = tid; idx < TE * EAD; idx += BT) {
        int e = idx & 15, i = idx >> 4;
        eat[i * 16 + e] = edge_attr[(size_t)(e0 + e) * EAD + i];
    }
    __syncthreads();

    // ---- Phase 1: s0t (transposed) + stage gated node features ----
    {
        const int e = tid & 15, q = tid >> 4;   // q = 0..15
        const int s = sidx[e], d = sidx[TE + e];
        const float* xs = x + (size_t)s * 256;
        const float* xd = x + (size_t)d * 256;

        float4 a = *(const float4*)(xs + q * 4);
        float4 b = *(const float4*)(xd + q * 4);
        s0t[(q*4+0)*16+e] = a.x; s0t[(q*4+1)*16+e] = a.y;
        s0t[(q*4+2)*16+e] = a.z; s0t[(q*4+3)*16+e] = a.w;
        s0t[(64+q*4+0)*16+e] = b.x; s0t[(64+q*4+1)*16+e] = b.y;
        s0t[(64+q*4+2)*16+e] = b.z; s0t[(64+q*4+3)*16+e] = b.w;

        float4 v0 = *(const float4*)(xs + 64 + q*12);
        float4 v1 = *(const float4*)(xs + 64 + q*12 + 4);
        float4 v2 = *(const float4*)(xs + 64 + q*12 + 8);
        float4 w0 = *(const float4*)(xd + 64 + q*12);
        float4 w1 = *(const float4*)(xd + 64 + q*12 + 4);
        float4 w2 = *(const float4*)(xd + 64 + q*12 + 8);
        float d0 = v0.x*w0.x + v0.y*w0.y + v0.z*w0.z;
        float d1 = v0.w*w0.w + v1.x*w1.x + v1.y*w1.y;
        float d2 = v1.z*w1.z + v1.w*w1.w + v2.x*w2.x;
        float d3 = v2.y*w2.y + v2.z*w2.z + v2.w*w2.w;
        s0t[(128+q*4+0)*16+e] = d0; s0t[(128+q*4+1)*16+e] = d1;
        s0t[(128+q*4+2)*16+e] = d2; s0t[(128+q*4+3)*16+e] = d3;

        float4 gs = *(const float4*)(g_sp + (size_t)s * 64 + q * 4);
        float4 gd = *(const float4*)(g_sp + (size_t)d * 64 + q * 4);
        spsT[(q*4+0)*16+e] = gs.x; spsT[(q*4+1)*16+e] = gs.y;
        spsT[(q*4+2)*16+e] = gs.z; spsT[(q*4+3)*16+e] = gs.w;
        spsT[(64+q*4+0)*16+e] = gd.x; spsT[(64+q*4+1)*16+e] = gd.y;
        spsT[(64+q*4+2)*16+e] = gd.z; spsT[(64+q*4+3)*16+e] = gd.w;

        {
            float4 p0 = *(const float4*)(g_vp + (size_t)s * 192 + q * 12);
            float4 p1 = *(const float4*)(g_vp + (size_t)s * 192 + q * 12 + 4);
            float4 p2 = *(const float4*)(g_vp + (size_t)s * 192 + q * 12 + 8);
            float pv[12] = {p0.x,p0.y,p0.z,p0.w,p1.x,p1.y,p1.z,p1.w,p2.x,p2.y,p2.z,p2.w};
            #pragma unroll
            for (int r = 0; r < 12; r++) vpsT[(q*12 + r)*16 + e] = pv[r];
        }
        {
            float4 p0 = *(const float4*)(g_vp + (size_t)d * 192 + q * 12);
            float4 p1 = *(const float4*)(g_vp + (size_t)d * 192 + q * 12 + 4);
            float4 p2 = *(const float4*)(g_vp + (size_t)d * 192 + q * 12 + 8);
            float pv[12] = {p0.x,p0.y,p0.z,p0.w,p1.x,p1.y,p1.z,p1.w,p2.x,p2.y,p2.z,p2.w};
            #pragma unroll
            for (int r = 0; r < 12; r++) vpsT[(192 + q*12 + r)*16 + e] = pv[r];
        }
    }
    __syncthreads();

    // ---- Phase 2: h1 = silu(s0@Ws1+bs1) [128 thr], r1 = silu(ea@Wr1+br1) [128 thr]
    // thread tile: 2 outputs x 8 edges. Warp lanes = consecutive output groups
    // (same edge half) -> activation LDS are warp broadcasts.
    {
        const int half = tid >> 7;         // 0 = s-branch, 1 = r-branch
        const int kg   = tid & 63;         // output pair: k = kg*2, kg*2+1
        const int eh   = (tid >> 6) & 1;   // edge half
        const float* W  = half ? Wr1 : Ws1;
        const float* bb = half ? br1 : bs1;
        const float* A  = half ? eat : s0t;
        const int    ni = half ? EAD : KS0;
        float* dst = half ? r1t : h1t;

        float b0 = bb[kg*2], b1 = bb[kg*2+1];
        u64 a0[4], a1[4];
        #pragma unroll
        for (int p = 0; p < 4; p++) { a0[p] = pk(b0, b0); a1[p] = pk(b1, b1); }

        #pragma unroll 2
        for (int i = 0; i < ni; i++) {
            float2 w = *(const float2*)(W + i * HID + kg * 2);
            u64 w0 = pk(w.x, w.x), w1 = pk(w.y, w.y);
            ulonglong2 p0 = *(const ulonglong2*)(A + i*16 + eh*8);
            ulonglong2 p1 = *(const ulonglong2*)(A + i*16 + eh*8 + 4);
            u64 act[4] = {p0.x, p0.y, p1.x, p1.y};
            #pragma unroll
            for (int p = 0; p < 4; p++) {
                fma2(a0[p], act[p], w0);
                fma2(a1[p], act[p], w1);
            }
        }
        float4 o0, o1; float2 q;
        q = up(a0[0]); o0.x = siluf(q.x); o0.y = siluf(q.y);
        q = up(a0[1]); o0.z = siluf(q.x); o0.w = siluf(q.y);
        q = up(a0[2]); o1.x = siluf(q.x); o1.y = siluf(q.y);
        q = up(a0[3]); o1.z = siluf(q.x); o1.w = siluf(q.y);
        *(float4*)(dst + (kg*2)*16 + eh*8)     = o0;
        *(float4*)(dst + (kg*2)*16 + eh*8 + 4) = o1;
        q = up(a1[0]); o0.x = siluf(q.x); o0.y = siluf(q.y);
        q = up(a1[1]); o0.z = siluf(q.x); o0.w = siluf(q.y);
        q = up(a1[2]); o1.x = siluf(q.x); o1.y = siluf(q.y);
        q = up(a1[3]); o1.z = siluf(q.x); o1.w = siluf(q.y);
        *(float4*)(dst + (kg*2+1)*16 + eh*8)     = o0;
        *(float4*)(dst + (kg*2+1)*16 + eh*8 + 4) = o1;
    }
    __syncthreads();

    // ---- Phase 3: tp_w = (h1@Ws2+bs2)*(r1@Wr2+br2)
    // 160 active threads: g=0 -> t-gemm (Ws2,h1), g=1 -> r-gemm (Wr2,r1).
    // Thread tile: 4 kv x 16 edges. Activation LDS broadcast (addr dep only on i,g).
    {
        const bool act3 = tid < 160;
        const int g   = tid < 80 ? 0 : 1;
        const int kvg = act3 ? (tid % 80) : 0;   // kv = kvg*4
        const float* W = g ? Wr2 : Ws2;
        const float* A = g ? r1t : h1t;

        u64 acc[4][8];
        #pragma unroll
        for (int kv = 0; kv < 4; kv++)
            #pragma unroll
            for (int p = 0; p < 8; p++) acc[kv][p] = pk(0.f, 0.f);

        if (act3) {
            #pragma unroll 2
            for (int i = 0; i < HID; i++) {
                float4 w = *(const float4*)(W + i * WN + kvg * 4);
                u64 w0 = pk(w.x, w.x), w1 = pk(w.y, w.y), w2 = pk(w.z, w.z), w3 = pk(w.w, w.w);
                ulonglong2 p0 = *(const ulonglong2*)(A + i*16);
                ulonglong2 p1 = *(const ulonglong2*)(A + i*16 + 4);
                ulonglong2 p2 = *(const ulonglong2*)(A + i*16 + 8);
                ulonglong2 p3 = *(const ulonglong2*)(A + i*16 + 12);
                u64 act[8] = {p0.x, p0.y, p1.x, p1.y, p2.x, p2.y, p3.x, p3.y};
                #pragma unroll
                for (int p = 0; p < 8; p++) {
                    fma2(acc[0][p], act[p], w0);
                    fma2(acc[1][p], act[p], w1);
                    fma2(acc[2][p], act[p], w2);
                    fma2(acc[3][p], act[p], w3);
                }
            }
            if (g == 1) {   // r-gemm writes (accr + br2) into tpwT
                #pragma unroll
                for (int kv = 0; kv < 4; kv++) {
                    float c2 = br2[kvg*4 + kv];
                    u64 cc = pk(c2, c2);
                    #pragma unroll
                    for (int p = 0; p < 8; p++) {
                        float2 q = up(acc[kv][p]);
                        *(u64*)(tpwT + (kvg*4+kv)*16 + p*2) = pk(q.x + c2, q.y + c2);
                    }
                    (void)cc;
                }
            }
        }
        __syncthreads();
        if (act3 && g == 0) {   // t-gemm combines
            #pragma unroll
            for (int kv = 0; kv < 4; kv++) {
                float b2 = bs2[kvg*4 + kv];
                #pragma unroll
                for (int p = 0; p < 8; p++) {
                    float2 t = up(acc[kv][p]);
                    float2 r = up(*(const u64*)(tpwT + (kvg*4+kv)*16 + p*2));
                    *(u64*)(tpwT + (kvg*4+kv)*16 + p*2) = pk((t.x + b2) * r.x, (t.y + b2) * r.y);
                }
            }
        }
    }
    __syncthreads();

    // ---- Phase 4a: out_v gated -> Vt[u*48 + c*16 + e] (overlays s0t/h1t/r1t) ----
    #pragma unroll
    for (int it = 0; it < 12; it++) {
        int idx = tid + it * 256;     // 3072 = 16 * 192
        int e = idx & 15, u = idx >> 4;
        float vx, vy, vz;
        if (u < 64) {
            float coef = tpwT[(64+u)*16+e] * spsT[u*16+e];
            vx = coef * vpsT[(192 +       u)*16+e];
            vy = coef * vpsT[(192 + 64  + u)*16+e];
            vz = coef * vpsT[(192 + 128 + u)*16+e];
        } else if (u < 128) {
            int uu = u - 64;
            float coef = tpwT[(128+uu)*16+e] * spsT[(64+uu)*16+e];
            vx = coef * vpsT[(      uu)*16+e];
            vy = coef * vpsT[( 64 + uu)*16+e];
            vz = coef * vpsT[(128 + uu)*16+e];
        } else {
            int uu = u - 128;
            float w5 = tpwT[(256+uu)*16+e] * INV_SQRT2;
            float ax = vpsT[uu*16+e],        ay = vpsT[(64+uu)*16+e],  az = vpsT[(128+uu)*16+e];
            float bx = vpsT[(192+uu)*16+e],  by = vpsT[(256+uu)*16+e], bz = vpsT[(320+uu)*16+e];
            vx = w5 * (ay*bz - az*by);
            vy = w5 * (az*bx - ax*bz);
            vz = w5 * (ax*by - ay*bx);
        }
        float nrm = sqrtf(vx*vx + vy*vy + vz*vz + 1e-12f);
        float g = siluf(nrm * gwp[u] + gbp[u]);
        Vt[u*48 +  0 + e] = vx * g;
        Vt[u*48 + 16 + e] = vy * g;
        Vt[u*48 + 32 + e] = vz * g;
    }

    // ---- Phase 4b: out_s -> outsT[j][e] ----
    #pragma unroll
    for (int it = 0; it < 8; it++) {
        int idx = tid + it * 256;     // 2048 = 16 * 128
        int e = idx & 15, j = idx >> 4;
        float val;
        if (j < 64) {
            val = tpwT[j*16+e] * spsT[j*16+e] * spsT[(64+j)*16+e];
        } else {
            int u = j - 64;
            float dt = vpsT[u*16+e]       * vpsT[(192+u)*16+e]
                     + vpsT[(64+u)*16+e]  * vpsT[(256+u)*16+e]
                     + vpsT[(128+u)*16+e] * vpsT[(320+u)*16+e];
            val = tpwT[(192+u)*16+e] * dt * INV_SQRT3;
        }
        outsT[j*16+e] = siluf(val);
    }
    __syncthreads();

    // ---- Phase 5: tid<128: fij_s = out_s @ W_post_s; tid>=128: fij_v ----
    if (tid < 128) {
        // tile: 2 v x 4 edges; lanes = v-groups -> broadcast acts
        const int vg = tid & 31;          // v = vg*2
        const int eq = tid >> 5;          // edges eq*4 .. +3
        u64 a0[2], a1[2];
        a0[0] = a0[1] = a1[0] = a1[1] = pk(0.f, 0.f);
        #pragma unroll 4
        for (int j = 0; j < TPS; j++) {
            float2 w = *(const float2*)(Wpost_s + j * NS + vg * 2);
            u64 w0 = pk(w.x, w.x), w1 = pk(w.y, w.y);
            ulonglong2 p = *(const ulonglong2*)(outsT + j*16 + eq*4);
            fma2(a0[0], p.x, w0); fma2(a0[1], p.y, w0);
            fma2(a1[0], p.x, w1); fma2(a1[1], p.y, w1);
        }
        #pragma unroll
        for (int vv = 0; vv < 2; vv++) {
            float2 q0 = up(vv ? a1[0] : a0[0]);
            float2 q1 = up(vv ? a1[1] : a0[1]);
            float vals[4] = {q0.x, q0.y, q1.x, q1.y};
            #pragma unroll
            for (int t = 0; t < 4; t++) {
                size_t o = (size_t)(e0 + eq*4 + t) * 256 + vg*2 + vv;
                out[o] = fij_in[o] + vals[t];
            }
        }
    } else {
        // tile: 2 v x 12 cols (of 48 = 3c x 16e); lanes = v-groups -> broadcast
        const int t2 = tid - 128;
        const int vg = t2 & 31;           // v = vg*2
        const int cg = t2 >> 5;           // cols cg*12 .. +11
        u64 a0[6], a1[6];
        #pragma unroll
        for (int p = 0; p < 6; p++) { a0[p] = pk(0.f, 0.f); a1[p] = a0[p]; }
        #pragma unroll 2
        for (int u = 0; u < TPV; u++) {
            float2 w = *(const float2*)(Wpost_v + u * NV + vg * 2);
            u64 w0 = pk(w.x, w.x), w1 = pk(w.y, w.y);
            ulonglong2 q0 = *(const ulonglong2*)(Vt + u*48 + cg*12);
            ulonglong2 q1 = *(const ulonglong2*)(Vt + u*48 + cg*12 + 4);
            ulonglong2 q2 = *(const ulonglong2*)(Vt + u*48 + cg*12 + 8);
            u64 act[6] = {q0.x, q0.y, q1.x, q1.y, q2.x, q2.y};
            #pragma unroll
            for (int p = 0; p < 6; p++) {
                fma2(a0[p], act[p], w0);
                fma2(a1[p], act[p], w1);
            }
        }
        #pragma unroll
        for (int p = 0; p < 6; p++) {
            float2 q0 = up(a0[p]), q1 = up(a1[p]);
            float vals[2][2] = {{q0.x, q0.y}, {q1.x, q1.y}};
            #pragma unroll
            for (int vv = 0; vv < 2; vv++) {
                #pragma unroll
                for (int h = 0; h < 2; h++) {
                    int col = cg*12 + p*2 + h;
                    int c = col >> 4, e = col & 15;
                    size_t o = (size_t)(e0 + e) * 256 + 64 + (size_t)(vg*2+vv) * 3 + c;
                    out[o] = fij_in[o] + vals[vv][h];
                }
            }
        }
    }
}

// ---------------------------------------------------------------------------
extern "C" void kernel_launch(void* const* d_in, const int* in_sizes, int n_in,
                              void* d_out, int out_size)
{
    const float* x         = (const float*)d_in[0];
    const float* edge_attr = (const float*)d_in[1];
    const float* fij_in    = (const float*)d_in[2];
    const float* W_pre_s   = (const float*)d_in[3];
    const float* b_pre_s   = (const float*)d_in[4];
    const float* W_pre_v   = (const float*)d_in[5];
    const float* gw_pre    = (const float*)d_in[6];
    const float* gb_pre    = (const float*)d_in[7];
    const float* Ws1       = (const float*)d_in[8];
    const float* bs1       = (const float*)d_in[9];
    const float* Ws2       = (const float*)d_in[10];
    const float* bs2       = (const float*)d_in[11];
    const float* Wr1       = (const float*)d_in[12];
    const float* br1       = (const float*)d_in[13];
    const float* Wr2       = (const float*)d_in[14];
    const float* br2       = (const float*)d_in[15];
    const float* gw_post   = (const float*)d_in[16];
    const float* gb_post   = (const float*)d_in[17];
    const float* W_post_s  = (const float*)d_in[18];
    const float* W_post_v  = (const float*)d_in[19];
    const int*   ei        = (const int*)d_in[20];

    const int N = in_sizes[0] / 256;
    const int E = in_sizes[2] / 256;

    node_kernel<<<(N + 3) / 4, 256>>>(x, W_pre_s, b_pre_s, W_pre_v, gw_pre, gb_pre, N);

    const size_t shm = (size_t)24928 * 4;   // 99712 B
    cudaFuncSetAttribute(edge_kernel, cudaFuncAttributeMaxDynamicSharedMemorySize, (int)shm);

    edge_kernel<<<E / TE, BT, shm>>>(
        x, edge_attr, fij_in,
        Ws1, bs1, Ws2, bs2, Wr1, br1, Wr2, br2,
        gw_post, gb_post, W_post_s, W_post_v,
        ei, (float*)d_out, E);
}

// round 4
// speedup vs baseline: 1.3163x; 1.2047x over previous
#include <cuda_runtime.h>
#include <cuda_bf16.h>

#define NN 10000
#define NS 64
#define NV 64
#define HID 128
#define WN 320
#define KS0 192
#define EAD 20
#define TPS 128
#define TPV 192

#define TE 16
#define BT 320

#define INV_SQRT3 0.5773502691896258f
#define INV_SQRT2 0.7071067811865476f

// smem offsets (floats)
#define OFF_S0T   0        // [192][16]
#define OFF_H1T   3072     // [128][20] padded rows
#define OFF_R1T   5632     // [128][20]
#define OFF_VT    0        // [192][48] overlays s0t/h1t/r1t after ph3
#define OFF_SPS   9216     // [128][16]
#define OFF_VPS   11264    // [384][16]
#define OFF_TPW   17408    // [320][20] padded rows
#define OFF_OUTS  23808    // [128][16]
#define OFF_EAT   25856    // [20][16]
#define OFF_IDX   26176    // 32 ints
#define SMEM_FLOATS 26208

typedef unsigned long long u64;

__device__ float g_sp[NN * NS];
__device__ float g_vp[NN * 3 * NV];   // [n][c*64+v]

__device__ __forceinline__ float siluf(float x) { return x / (1.0f + __expf(-x)); }
__device__ __forceinline__ void fma2(u64& d, u64 a, u64 b) {
    asm("fma.rn.f32x2 %0, %1, %2, %0;" : "+l"(d) : "l"(a), "l"(b));
}
__device__ __forceinline__ u64 pk(float x, float y) {
    u64 r; asm("mov.b64 %0, {%1, %2};" : "=l"(r) : "f"(x), "f"(y)); return r;
}
__device__ __forceinline__ float2 up(u64 a) {
    float2 r; asm("mov.b64 {%0, %1}, %2;" : "=f"(r.x), "=f"(r.y) : "l"(a)); return r;
}

// ---------------------------------------------------------------------------
__global__ __launch_bounds__(256) void node_kernel(
    const float* __restrict__ x,
    const float* __restrict__ Wps, const float* __restrict__ bps,
    const float* __restrict__ Wpv,
    const float* __restrict__ gw, const float* __restrict__ gb,
    int N)
{
    __shared__ float sx[4][256];
    const int ln = threadIdx.x >> 6;
    const int v  = threadIdx.x & 63;
    const int n  = blockIdx.x * 4 + ln;

    if (n < N) {
        #pragma unroll
        for (int i = v; i < 256; i += 64) sx[ln][i] = x[n * 256 + i];
    }
    __syncthreads();
    if (n >= N) return;

    const float* xs = sx[ln];
    const float* xv = sx[ln] + 64;

    float sacc = bps[v];
    #pragma unroll 4
    for (int i = 0; i < NS; i++) sacc = fmaf(xs[i], Wps[i * NS + v], sacc);

    float ax = 0.f, ay = 0.f, az = 0.f;
    #pragma unroll 4
    for (int u = 0; u < NV; u++) {
        float w = Wpv[u * NV + v];
        ax = fmaf(xv[u * 3 + 0], w, ax);
        ay = fmaf(xv[u * 3 + 1], w, ay);
        az = fmaf(xv[u * 3 + 2], w, az);
    }
    float nrm = sqrtf(ax * ax + ay * ay + az * az + 1e-12f);
    float g = siluf(nrm * gw[v] + gb[v]);

    g_sp[n * NS + v] = siluf(sacc);
    g_vp[n * 192 + 0 * 64 + v] = ax * g;
    g_vp[n * 192 + 1 * 64 + v] = ay * g;
    g_vp[n * 192 + 2 * 64 + v] = az * g;
}

// ---------------------------------------------------------------------------
__global__ __launch_bounds__(BT, 2) void edge_kernel(
    const float* __restrict__ x,
    const float* __restrict__ edge_attr,
    const float* __restrict__ fij_in,
    const float* __restrict__ Ws1, const float* __restrict__ bs1,
    const float* __restrict__ Ws2, const float* __restrict__ bs2,
    const float* __restrict__ Wr1, const float* __restrict__ br1,
    const float* __restrict__ Wr2, const float* __restrict__ br2,
    const float* __restrict__ gwp, const float* __restrict__ gbp,
    const float* __restrict__ Wpost_s, const float* __restrict__ Wpost_v,
    const int* __restrict__ ei,
    float* __restrict__ out, int E)
{
    extern __shared__ float sm[];
    float* s0t   = sm + OFF_S0T;
    float* h1t   = sm + OFF_H1T;
    float* r1t   = sm + OFF_R1T;
    float* Vt    = sm + OFF_VT;
    float* spsT  = sm + OFF_SPS;
    float* vpsT  = sm + OFF_VPS;
    float* tpwT  = sm + OFF_TPW;
    float* outsT = sm + OFF_OUTS;
    float* eat   = sm + OFF_EAT;
    int*   sidx  = (int*)(sm + OFF_IDX);

    const int tid = threadIdx.x;
    const int e0  = blockIdx.x * TE;

    if (tid < 32) {
        int e = tid & 15;
        sidx[tid] = (tid < 16) ? ei[e0 + e] : ei[E + e0 + e];
    }
    __syncthreads();

    // ---- Phase 1 (tid<256): gather x, g_sp, g_vp; (tid>=256): load edge_attr ----
    if (tid < 256) {
        const int e = tid & 15, q = tid >> 4;
        const int s = sidx[e], d = sidx[TE + e];
        const float* xs = x + (size_t)s * 256;
        const float* xd = x + (size_t)d * 256;

        float4 a = *(const float4*)(xs + q * 4);
        float4 b = *(const float4*)(xd + q * 4);
        s0t[(q*4+0)*16+e] = a.x; s0t[(q*4+1)*16+e] = a.y;
        s0t[(q*4+2)*16+e] = a.z; s0t[(q*4+3)*16+e] = a.w;
        s0t[(64+q*4+0)*16+e] = b.x; s0t[(64+q*4+1)*16+e] = b.y;
        s0t[(64+q*4+2)*16+e] = b.z; s0t[(64+q*4+3)*16+e] = b.w;

        float4 v0 = *(const float4*)(xs + 64 + q*12);
        float4 v1 = *(const float4*)(xs + 64 + q*12 + 4);
        float4 v2 = *(const float4*)(xs + 64 + q*12 + 8);
        float4 w0 = *(const float4*)(xd + 64 + q*12);
        float4 w1 = *(const float4*)(xd + 64 + q*12 + 4);
        float4 w2 = *(const float4*)(xd + 64 + q*12 + 8);
        float d0 = v0.x*w0.x + v0.y*w0.y + v0.z*w0.z;
        float d1 = v0.w*w0.w + v1.x*w1.x + v1.y*w1.y;
        float d2 = v1.z*w1.z + v1.w*w1.w + v2.x*w2.x;
        float d3 = v2.y*w2.y + v2.z*w2.z + v2.w*w2.w;
        s0t[(128+q*4+0)*16+e] = d0; s0t[(128+q*4+1)*16+e] = d1;
        s0t[(128+q*4+2)*16+e] = d2; s0t[(128+q*4+3)*16+e] = d3;

        float4 gs = *(const float4*)(g_sp + (size_t)s * 64 + q * 4);
        float4 gd = *(const float4*)(g_sp + (size_t)d * 64 + q * 4);
        spsT[(q*4+0)*16+e] = gs.x; spsT[(q*4+1)*16+e] = gs.y;
        spsT[(q*4+2)*16+e] = gs.z; spsT[(q*4+3)*16+e] = gs.w;
        spsT[(64+q*4+0)*16+e] = gd.x; spsT[(64+q*4+1)*16+e] = gd.y;
        spsT[(64+q*4+2)*16+e] = gd.z; spsT[(64+q*4+3)*16+e] = gd.w;

        {
            float4 p0 = *(const float4*)(g_vp + (size_t)s * 192 + q * 12);
            float4 p1 = *(const float4*)(g_vp + (size_t)s * 192 + q * 12 + 4);
            float4 p2 = *(const float4*)(g_vp + (size_t)s * 192 + q * 12 + 8);
            float pv[12] = {p0.x,p0.y,p0.z,p0.w,p1.x,p1.y,p1.z,p1.w,p2.x,p2.y,p2.z,p2.w};
            #pragma unroll
            for (int r = 0; r < 12; r++) vpsT[(q*12 + r)*16 + e] = pv[r];
        }
        {
            float4 p0 = *(const float4*)(g_vp + (size_t)d * 192 + q * 12);
            float4 p1 = *(const float4*)(g_vp + (size_t)d * 192 + q * 12 + 4);
            float4 p2 = *(const float4*)(g_vp + (size_t)d * 192 + q * 12 + 8);
            float pv[12] = {p0.x,p0.y,p0.z,p0.w,p1.x,p1.y,p1.z,p1.w,p2.x,p2.y,p2.z,p2.w};
            #pragma unroll
            for (int r = 0; r < 12; r++) vpsT[(192 + q*12 + r)*16 + e] = pv[r];
        }
    } else {
        for (int idx = tid - 256; idx < TE * EAD; idx += 64) {
            int e = idx & 15, i = idx >> 4;
            eat[idx] = edge_attr[(size_t)(e0 + e) * EAD + i];
        }
    }
    __syncthreads();

    // ---- Phase 2 (tid<256): h1/r1; thread = (k, edge-half), both branches ----
    if (tid < 256) {
        const int k  = tid & 127;
        const int eh = tid >> 7;
        // s-branch (192 iters)
        {
            float bk = bs1[k];
            u64 a0 = pk(bk,bk), a1 = a0, a2 = a0, a3 = a0;
            for (int ib = 0; ib < KS0; ib += 4) {
                float w[4];
                #pragma unroll
                for (int j = 0; j < 4; j++) w[j] = Ws1[(ib+j) * HID + k];
                #pragma unroll
                for (int j = 0; j < 4; j++) {
                    u64 ww = pk(w[j], w[j]);
                    ulonglong2 p0 = *(const ulonglong2*)(s0t + (ib+j)*16 + eh*8);
                    ulonglong2 p1 = *(const ulonglong2*)(s0t + (ib+j)*16 + eh*8 + 4);
                    fma2(a0, p0.x, ww); fma2(a1, p0.y, ww);
                    fma2(a2, p1.x, ww); fma2(a3, p1.y, ww);
                }
            }
            float4 o0, o1; float2 q;
            q = up(a0); o0.x = siluf(q.x); o0.y = siluf(q.y);
            q = up(a1); o0.z = siluf(q.x); o0.w = siluf(q.y);
            q = up(a2); o1.x = siluf(q.x); o1.y = siluf(q.y);
            q = up(a3); o1.z = siluf(q.x); o1.w = siluf(q.y);
            *(float4*)(h1t + k*20 + eh*8)     = o0;
            *(float4*)(h1t + k*20 + eh*8 + 4) = o1;
        }
        // r-branch (20 iters)
        {
            float bk = br1[k];
            u64 a0 = pk(bk,bk), a1 = a0, a2 = a0, a3 = a0;
            for (int ib = 0; ib < EAD; ib += 4) {
                float w[4];
                #pragma unroll
                for (int j = 0; j < 4; j++) w[j] = Wr1[(ib+j) * HID + k];
                #pragma unroll
                for (int j = 0; j < 4; j++) {
                    u64 ww = pk(w[j], w[j]);
                    ulonglong2 p0 = *(const ulonglong2*)(eat + (ib+j)*16 + eh*8);
                    ulonglong2 p1 = *(const ulonglong2*)(eat + (ib+j)*16 + eh*8 + 4);
                    fma2(a0, p0.x, ww); fma2(a1, p0.y, ww);
                    fma2(a2, p1.x, ww); fma2(a3, p1.y, ww);
                }
            }
            float4 o0, o1; float2 q;
            q = up(a0); o0.x = siluf(q.x); o0.y = siluf(q.y);
            q = up(a1); o0.z = siluf(q.x); o0.w = siluf(q.y);
            q = up(a2); o1.x = siluf(q.x); o1.y = siluf(q.y);
            q = up(a3); o1.z = siluf(q.x); o1.w = siluf(q.y);
            *(float4*)(r1t + k*20 + eh*8)     = o0;
            *(float4*)(r1t + k*20 + eh*8 + 4) = o1;
        }
    }
    __syncthreads();

    // ---- Phase 3: tp_w; thread = 1 kv, 16 edges, both branches (320 thr) ----
    {
        const int kv = tid;
        u64 at[8], ar[8];
        #pragma unroll
        for (int p = 0; p < 8; p++) { at[p] = pk(0.f,0.f); ar[p] = at[p]; }
        for (int ib = 0; ib < HID; ib += 4) {
            float wt[4], wr[4];
            #pragma unroll
            for (int j = 0; j < 4; j++) {
                wt[j] = Ws2[(ib+j) * WN + kv];
                wr[j] = Wr2[(ib+j) * WN + kv];
            }
            #pragma unroll
            for (int j = 0; j < 4; j++) {
                u64 w2t = pk(wt[j], wt[j]);
                ulonglong2 h0 = *(const ulonglong2*)(h1t + (ib+j)*20);
                ulonglong2 h1 = *(const ulonglong2*)(h1t + (ib+j)*20 + 4);
                ulonglong2 h2 = *(const ulonglong2*)(h1t + (ib+j)*20 + 8);
                ulonglong2 h3 = *(const ulonglong2*)(h1t + (ib+j)*20 + 12);
                fma2(at[0], h0.x, w2t); fma2(at[1], h0.y, w2t);
                fma2(at[2], h1.x, w2t); fma2(at[3], h1.y, w2t);
                fma2(at[4], h2.x, w2t); fma2(at[5], h2.y, w2t);
                fma2(at[6], h3.x, w2t); fma2(at[7], h3.y, w2t);
                u64 w2r = pk(wr[j], wr[j]);
                ulonglong2 r0 = *(const ulonglong2*)(r1t + (ib+j)*20);
                ulonglong2 r1 = *(const ulonglong2*)(r1t + (ib+j)*20 + 4);
                ulonglong2 r2 = *(const ulonglong2*)(r1t + (ib+j)*20 + 8);
                ulonglong2 r3 = *(const ulonglong2*)(r1t + (ib+j)*20 + 12);
                fma2(ar[0], r0.x, w2r); fma2(ar[1], r0.y, w2r);
                fma2(ar[2], r1.x, w2r); fma2(ar[3], r1.y, w2r);
                fma2(ar[4], r2.x, w2r); fma2(ar[5], r2.y, w2r);
                fma2(ar[6], r3.x, w2r); fma2(ar[7], r3.y, w2r);
            }
        }
        float b2 = bs2[kv], c2 = br2[kv];
        #pragma unroll
        for (int p = 0; p < 8; p++) {
            float2 t = up(at[p]), r = up(ar[p]);
            *(u64*)(tpwT + kv*20 + p*2) = pk((t.x + b2) * (r.x + c2),
                                             (t.y + b2) * (r.y + c2));
        }
    }
    __syncthreads();

    // ---- Phase 4a: out_v gated -> Vt[u][3c x 16e] ----
    for (int idx = tid; idx < TE * TPV; idx += BT) {
        int e = idx & 15, u = idx >> 4;
        float vx, vy, vz;
        if (u < 64) {
            float coef = tpwT[(64+u)*20+e] * spsT[u*16+e];
            vx = coef * vpsT[(192 +       u)*16+e];
            vy = coef * vpsT[(192 + 64  + u)*16+e];
            vz = coef * vpsT[(192 + 128 + u)*16+e];
        } else if (u < 128) {
            int uu = u - 64;
            float coef = tpwT[(128+uu)*20+e] * spsT[(64+uu)*16+e];
            vx = coef * vpsT[(      uu)*16+e];
            vy = coef * vpsT[( 64 + uu)*16+e];
            vz = coef * vpsT[(128 + uu)*16+e];
        } else {
            int uu = u - 128;
            float w5 = tpwT[(256+uu)*20+e] * INV_SQRT2;
            float ax = vpsT[uu*16+e],       ay = vpsT[(64+uu)*16+e],  az = vpsT[(128+uu)*16+e];
            float bx = vpsT[(192+uu)*16+e], by = vpsT[(256+uu)*16+e], bz = vpsT[(320+uu)*16+e];
            vx = w5 * (ay*bz - az*by);
            vy = w5 * (az*bx - ax*bz);
            vz = w5 * (ax*by - ay*bx);
        }
        float nrm = sqrtf(vx*vx + vy*vy + vz*vz + 1e-12f);
        float g = siluf(nrm * gwp[u] + gbp[u]);
        Vt[u*48 +  0 + e] = vx * g;
        Vt[u*48 + 16 + e] = vy * g;
        Vt[u*48 + 32 + e] = vz * g;
    }

    // ---- Phase 4b: out_s -> outsT[j][e] ----
    for (int idx = tid; idx < TE * TPS; idx += BT) {
        int e = idx & 15, j = idx >> 4;
        float val;
        if (j < 64) {
            val = tpwT[j*20+e] * spsT[j*16+e] * spsT[(64+j)*16+e];
        } else {
            int u = j - 64;
            float dt = vpsT[u*16+e]       * vpsT[(192+u)*16+e]
                     + vpsT[(64+u)*16+e]  * vpsT[(256+u)*16+e]
                     + vpsT[(128+u)*16+e] * vpsT[(320+u)*16+e];
            val = tpwT[(192+u)*20+e] * dt * INV_SQRT3;
        }
        outsT[j*16+e] = siluf(val);
    }
    __syncthreads();

    // ---- Phase 5: tid<256 -> fij_v (1v x 12 cols); tid>=256 -> fij_s (1v x 16e) ----
    if (tid < 256) {
        const int v  = tid & 63;
        const int cg = tid >> 6;   // cols cg*12 .. +11 of 48
        u64 acc[6];
        #pragma unroll
        for (int p = 0; p < 6; p++) acc[p] = pk(0.f, 0.f);
        for (int ub = 0; ub < TPV; ub += 4) {
            float w[4];
            #pragma unroll
            for (int j = 0; j < 4; j++) w[j] = Wpost_v[(ub+j) * NV + v];
            #pragma unroll
            for (int j = 0; j < 4; j++) {
                u64 ww = pk(w[j], w[j]);
                ulonglong2 q0 = *(const ulonglong2*)(Vt + (ub+j)*48 + cg*12);
                ulonglong2 q1 = *(const ulonglong2*)(Vt + (ub+j)*48 + cg*12 + 4);
                ulonglong2 q2 = *(const ulonglong2*)(Vt + (ub+j)*48 + cg*12 + 8);
                fma2(acc[0], q0.x, ww); fma2(acc[1], q0.y, ww);
                fma2(acc[2], q1.x, ww); fma2(acc[3], q1.y, ww);
                fma2(acc[4], q2.x, ww); fma2(acc[5], q2.y, ww);
            }
        }
        #pragma unroll
        for (int p = 0; p < 6; p++) {
            float2 q = up(acc[p]);
            float vals[2] = {q.x, q.y};
            #pragma unroll
            for (int h = 0; h < 2; h++) {
                int col = cg*12 + p*2 + h;
                int c = col >> 4, e = col & 15;
                size_t o = (size_t)(e0 + e) * 256 + 64 + (size_t)v * 3 + c;
                out[o] = fij_in[o] + vals[h];
            }
        }
    } else {
        const int v = tid - 256;   // 0..63
        u64 acc[8];
        #pragma unroll
        for (int p = 0; p < 8; p++) acc[p] = pk(0.f, 0.f);
        for (int jb = 0; jb < TPS; jb += 4) {
            float w[4];
            #pragma unroll
            for (int j = 0; j < 4; j++) w[j] = Wpost_s[(jb+j) * NS + v];
            #pragma unroll
            for (int j = 0; j < 4; j++) {
                u64 ww = pk(w[j], w[j]);
                ulonglong2 q0 = *(const ulonglong2*)(outsT + (jb+j)*16);
                ulonglong2 q1 = *(const ulonglong2*)(outsT + (jb+j)*16 + 4);
                ulonglong2 q2 = *(const ulonglong2*)(outsT + (jb+j)*16 + 8);
                ulonglong2 q3 = *(const ulonglong2*)(outsT + (jb+j)*16 + 12);
                fma2(acc[0], q0.x, ww); fma2(acc[1], q0.y, ww);
                fma2(acc[2], q1.x, ww); fma2(acc[3], q1.y, ww);
                fma2(acc[4], q2.x, ww); fma2(acc[5], q2.y, ww);
                fma2(acc[6], q3.x, ww); fma2(acc[7], q3.y, ww);
            }
        }
        #pragma unroll
        for (int p = 0; p < 8; p++) {
            float2 q = up(acc[p]);
            size_t o0 = (size_t)(e0 + p*2)     * 256 + v;
            size_t o1 = (size_t)(e0 + p*2 + 1) * 256 + v;
            out[o0] = fij_in[o0] + q.x;
            out[o1] = fij_in[o1] + q.y;
        }
    }
}

// ---------------------------------------------------------------------------
extern "C" void kernel_launch(void* const* d_in, const int* in_sizes, int n_in,
                              void* d_out, int out_size)
{
    const float* x         = (const float*)d_in[0];
    const float* edge_attr = (const float*)d_in[1];
    const float* fij_in    = (const float*)d_in[2];
    const float* W_pre_s   = (const float*)d_in[3];
    const float* b_pre_s   = (const float*)d_in[4];
    const float* W_pre_v   = (const float*)d_in[5];
    const float* gw_pre    = (const float*)d_in[6];
    const float* gb_pre    = (const float*)d_in[7];
    const float* Ws1       = (const float*)d_in[8];
    const float* bs1       = (const float*)d_in[9];
    const float* Ws2       = (const float*)d_in[10];
    const float* bs2       = (const float*)d_in[11];
    const float* Wr1       = (const float*)d_in[12];
    const float* br1       = (const float*)d_in[13];
    const float* Wr2       = (const float*)d_in[14];
    const float* br2       = (const float*)d_in[15];
    const float* gw_post   = (const float*)d_in[16];
    const float* gb_post   = (const float*)d_in[17];
    const float* W_post_s  = (const float*)d_in[18];
    const float* W_post_v  = (const float*)d_in[19];
    const int*   ei        = (const int*)d_in[20];

    const int N = in_sizes[0] / 256;
    const int E = in_sizes[2] / 256;

    node_kernel<<<(N + 3) / 4, 256>>>(x, W_pre_s, b_pre_s, W_pre_v, gw_pre, gb_pre, N);

    const size_t shm = (size_t)SMEM_FLOATS * 4;   // 104832 B
    cudaFuncSetAttribute(edge_kernel, cudaFuncAttributeMaxDynamicSharedMemorySize, (int)shm);

    edge_kernel<<<E / TE, BT, shm>>>(
        x, edge_attr, fij_in,
        Ws1, bs1, Ws2, bs2, Wr1, br1, Wr2, br2,
        gw_post, gb_post, W_post_s, W_post_v,
        ei, (float*)d_out, E);
}

// round 5
// speedup vs baseline: 1.3214x; 1.0039x over previous
#include <cuda_runtime.h>
#include <cuda_bf16.h>

#define NN 10000
#define NS 64
#define NV 64
#define HID 128
#define WN 320
#define KS0 192
#define EAD 20
#define TPS 128
#define TPV 192

#define TE 16
#define BT 320

#define INV_SQRT3 0.5773502691896258f
#define INV_SQRT2 0.7071067811865476f

// smem offsets (floats)
#define OFF_S0T   0        // [192][16]
#define OFF_H1T   3072     // [128][20] padded rows
#define OFF_R1T   5632     // [128][20]
#define OFF_VT    0        // [192][48] overlays s0t/h1t/r1t after ph3
#define OFF_SPS   9216     // [128][16]
#define OFF_VPS   11264    // [384][16]
#define OFF_TPW   17408    // [320][20] padded rows
#define OFF_OUTS  23808    // [128][16]
#define OFF_EAT   25856    // [20][16]
#define OFF_IDX   26176    // 32 ints
#define SMEM_FLOATS 26208

typedef unsigned long long u64;

__device__ float g_sp[NN * NS];
__device__ float g_vp[NN * 3 * NV];   // [n][c*64+v]

__device__ __forceinline__ float siluf(float x) { return x / (1.0f + __expf(-x)); }
__device__ __forceinline__ void fma2(u64& d, u64 a, u64 b) {
    asm("fma.rn.f32x2 %0, %1, %2, %0;" : "+l"(d) : "l"(a), "l"(b));
}
__device__ __forceinline__ u64 pk(float x, float y) {
    u64 r; asm("mov.b64 %0, {%1, %2};" : "=l"(r) : "f"(x), "f"(y)); return r;
}
__device__ __forceinline__ float2 up(u64 a) {
    float2 r; asm("mov.b64 {%0, %1}, %2;" : "=f"(r.x), "=f"(r.y) : "l"(a)); return r;
}

// ---------------------------------------------------------------------------
__global__ __launch_bounds__(256) void node_kernel(
    const float* __restrict__ x,
    const float* __restrict__ Wps, const float* __restrict__ bps,
    const float* __restrict__ Wpv,
    const float* __restrict__ gw, const float* __restrict__ gb,
    int N)
{
    __shared__ float sx[4][256];
    const int ln = threadIdx.x >> 6;
    const int v  = threadIdx.x & 63;
    const int n  = blockIdx.x * 4 + ln;

    if (n < N) {
        #pragma unroll
        for (int i = v; i < 256; i += 64) sx[ln][i] = x[n * 256 + i];
    }
    __syncthreads();
    if (n >= N) return;

    const float* xs = sx[ln];
    const float* xv = sx[ln] + 64;

    float sacc = bps[v];
    #pragma unroll 4
    for (int i = 0; i < NS; i++) sacc = fmaf(xs[i], Wps[i * NS + v], sacc);

    float ax = 0.f, ay = 0.f, az = 0.f;
    #pragma unroll 4
    for (int u = 0; u < NV; u++) {
        float w = Wpv[u * NV + v];
        ax = fmaf(xv[u * 3 + 0], w, ax);
        ay = fmaf(xv[u * 3 + 1], w, ay);
        az = fmaf(xv[u * 3 + 2], w, az);
    }
    float nrm = sqrtf(ax * ax + ay * ay + az * az + 1e-12f);
    float g = siluf(nrm * gw[v] + gb[v]);

    g_sp[n * NS + v] = siluf(sacc);
    g_vp[n * 192 + 0 * 64 + v] = ax * g;
    g_vp[n * 192 + 1 * 64 + v] = ay * g;
    g_vp[n * 192 + 2 * 64 + v] = az * g;
}

// ---------------------------------------------------------------------------
__global__ __launch_bounds__(BT, 2) void edge_kernel(
    const float* __restrict__ x,
    const float* __restrict__ edge_attr,
    const float* __restrict__ fij_in,
    const float* __restrict__ Ws1, const float* __restrict__ bs1,
    const float* __restrict__ Ws2, const float* __restrict__ bs2,
    const float* __restrict__ Wr1, const float* __restrict__ br1,
    const float* __restrict__ Wr2, const float* __restrict__ br2,
    const float* __restrict__ gwp, const float* __restrict__ gbp,
    const float* __restrict__ Wpost_s, const float* __restrict__ Wpost_v,
    const int* __restrict__ ei,
    float* __restrict__ out, int E)
{
    extern __shared__ float sm[];
    float* s0t   = sm + OFF_S0T;
    float* h1t   = sm + OFF_H1T;
    float* r1t   = sm + OFF_R1T;
    float* Vt    = sm + OFF_VT;
    float* spsT  = sm + OFF_SPS;
    float* vpsT  = sm + OFF_VPS;
    float* tpwT  = sm + OFF_TPW;
    float* outsT = sm + OFF_OUTS;
    float* eat   = sm + OFF_EAT;
    int*   sidx  = (int*)(sm + OFF_IDX);

    const int tid = threadIdx.x;
    const int e0  = blockIdx.x * TE;

    if (tid < 32) {
        int e = tid & 15;
        sidx[tid] = (tid < 16) ? ei[e0 + e] : ei[E + e0 + e];
    }
    __syncthreads();

    // ---- Phase 1 (tid<256): gather x, g_sp, g_vp; (tid>=256): load edge_attr ----
    if (tid < 256) {
        const int e = tid & 15, q = tid >> 4;
        const int s = sidx[e], d = sidx[TE + e];
        const float* xs = x + (size_t)s * 256;
        const float* xd = x + (size_t)d * 256;

        float4 a = *(const float4*)(xs + q * 4);
        float4 b = *(const float4*)(xd + q * 4);
        s0t[(q*4+0)*16+e] = a.x; s0t[(q*4+1)*16+e] = a.y;
        s0t[(q*4+2)*16+e] = a.z; s0t[(q*4+3)*16+e] = a.w;
        s0t[(64+q*4+0)*16+e] = b.x; s0t[(64+q*4+1)*16+e] = b.y;
        s0t[(64+q*4+2)*16+e] = b.z; s0t[(64+q*4+3)*16+e] = b.w;

        float4 v0 = *(const float4*)(xs + 64 + q*12);
        float4 v1 = *(const float4*)(xs + 64 + q*12 + 4);
        float4 v2 = *(const float4*)(xs + 64 + q*12 + 8);
        float4 w0 = *(const float4*)(xd + 64 + q*12);
        float4 w1 = *(const float4*)(xd + 64 + q*12 + 4);
        float4 w2 = *(const float4*)(xd + 64 + q*12 + 8);
        float d0 = v0.x*w0.x + v0.y*w0.y + v0.z*w0.z;
        float d1 = v0.w*w0.w + v1.x*w1.x + v1.y*w1.y;
        float d2 = v1.z*w1.z + v1.w*w1.w + v2.x*w2.x;
        float d3 = v2.y*w2.y + v2.z*w2.z + v2.w*w2.w;
        s0t[(128+q*4+0)*16+e] = d0; s0t[(128+q*4+1)*16+e] = d1;
        s0t[(128+q*4+2)*16+e] = d2; s0t[(128+q*4+3)*16+e] = d3;

        float4 gs = *(const float4*)(g_sp + (size_t)s * 64 + q * 4);
        float4 gd = *(const float4*)(g_sp + (size_t)d * 64 + q * 4);
        spsT[(q*4+0)*16+e] = gs.x; spsT[(q*4+1)*16+e] = gs.y;
        spsT[(q*4+2)*16+e] = gs.z; spsT[(q*4+3)*16+e] = gs.w;
        spsT[(64+q*4+0)*16+e] = gd.x; spsT[(64+q*4+1)*16+e] = gd.y;
        spsT[(64+q*4+2)*16+e] = gd.z; spsT[(64+q*4+3)*16+e] = gd.w;

        {
            float4 p0 = *(const float4*)(g_vp + (size_t)s * 192 + q * 12);
            float4 p1 = *(const float4*)(g_vp + (size_t)s * 192 + q * 12 + 4);
            float4 p2 = *(const float4*)(g_vp + (size_t)s * 192 + q * 12 + 8);
            float pv[12] = {p0.x,p0.y,p0.z,p0.w,p1.x,p1.y,p1.z,p1.w,p2.x,p2.y,p2.z,p2.w};
            #pragma unroll
            for (int r = 0; r < 12; r++) vpsT[(q*12 + r)*16 + e] = pv[r];
        }
        {
            float4 p0 = *(const float4*)(g_vp + (size_t)d * 192 + q * 12);
            float4 p1 = *(const float4*)(g_vp + (size_t)d * 192 + q * 12 + 4);
            float4 p2 = *(const float4*)(g_vp + (size_t)d * 192 + q * 12 + 8);
            float pv[12] = {p0.x,p0.y,p0.z,p0.w,p1.x,p1.y,p1.z,p1.w,p2.x,p2.y,p2.z,p2.w};
            #pragma unroll
            for (int r = 0; r < 12; r++) vpsT[(192 + q*12 + r)*16 + e] = pv[r];
        }
    } else {
        for (int idx = tid - 256; idx < TE * EAD; idx += 64) {
            eat[idx] = edge_attr[(size_t)(e0 + (idx & 15)) * EAD + (idx >> 4)];
        }
    }
    __syncthreads();

    // ---- Phase 2 (tid<256): thread = 2 k x 4 edges, both branches ----
    if (tid < 256) {
        const int kp = tid >> 2;   // k = kp*2, kp*2+1
        const int eq = tid & 3;    // edges eq*4..+3
        // s-branch (192 k-steps)
        {
            float2 bb = *(const float2*)(bs1 + kp*2);
            u64 a0[2] = {pk(bb.x,bb.x), pk(bb.x,bb.x)};
            u64 a1[2] = {pk(bb.y,bb.y), pk(bb.y,bb.y)};
            for (int i = 0; i < KS0; i += 2) {
                #pragma unroll
                for (int j = 0; j < 2; j++) {
                    float2 w = *(const float2*)(Ws1 + (i+j)*HID + kp*2);
                    ulonglong2 aa = *(const ulonglong2*)(s0t + (i+j)*16 + eq*4);
                    u64 w0 = pk(w.x,w.x), w1 = pk(w.y,w.y);
                    fma2(a0[0], aa.x, w0); fma2(a0[1], aa.y, w0);
                    fma2(a1[0], aa.x, w1); fma2(a1[1], aa.y, w1);
                }
            }
            float2 q0 = up(a0[0]), q1 = up(a0[1]);
            *(u64*)(h1t + (kp*2)*20 + eq*4)     = pk(siluf(q0.x), siluf(q0.y));
            *(u64*)(h1t + (kp*2)*20 + eq*4 + 2) = pk(siluf(q1.x), siluf(q1.y));
            q0 = up(a1[0]); q1 = up(a1[1]);
            *(u64*)(h1t + (kp*2+1)*20 + eq*4)     = pk(siluf(q0.x), siluf(q0.y));
            *(u64*)(h1t + (kp*2+1)*20 + eq*4 + 2) = pk(siluf(q1.x), siluf(q1.y));
        }
        // r-branch (20 k-steps)
        {
            float2 bb = *(const float2*)(br1 + kp*2);
            u64 a0[2] = {pk(bb.x,bb.x), pk(bb.x,bb.x)};
            u64 a1[2] = {pk(bb.y,bb.y), pk(bb.y,bb.y)};
            #pragma unroll 4
            for (int i = 0; i < EAD; i++) {
                float2 w = *(const float2*)(Wr1 + i*HID + kp*2);
                ulonglong2 aa = *(const ulonglong2*)(eat + i*16 + eq*4);
                u64 w0 = pk(w.x,w.x), w1 = pk(w.y,w.y);
                fma2(a0[0], aa.x, w0); fma2(a0[1], aa.y, w0);
                fma2(a1[0], aa.x, w1); fma2(a1[1], aa.y, w1);
            }
            float2 q0 = up(a0[0]), q1 = up(a0[1]);
            *(u64*)(r1t + (kp*2)*20 + eq*4)     = pk(siluf(q0.x), siluf(q0.y));
            *(u64*)(r1t + (kp*2)*20 + eq*4 + 2) = pk(siluf(q1.x), siluf(q1.y));
            q0 = up(a1[0]); q1 = up(a1[1]);
            *(u64*)(r1t + (kp*2+1)*20 + eq*4)     = pk(siluf(q0.x), siluf(q0.y));
            *(u64*)(r1t + (kp*2+1)*20 + eq*4 + 2) = pk(siluf(q1.x), siluf(q1.y));
        }
    }
    __syncthreads();

    // ---- Phase 3: thread = 4 kv x 4 edges, both branches (320 threads) ----
    {
        const int kvg = tid >> 2;   // kv = kvg*4..+3
        const int eq  = tid & 3;    // edges eq*4..+3
        u64 att[4][2], arr[4][2];
        #pragma unroll
        for (int kv = 0; kv < 4; kv++) {
            att[kv][0] = att[kv][1] = pk(0.f, 0.f);
            arr[kv][0] = arr[kv][1] = pk(0.f, 0.f);
        }
        for (int i = 0; i < HID; i += 2) {
            #pragma unroll
            for (int j = 0; j < 2; j++) {
                float4 wt = *(const float4*)(Ws2 + (i+j)*WN + kvg*4);
                float4 wr = *(const float4*)(Wr2 + (i+j)*WN + kvg*4);
                ulonglong2 hh = *(const ulonglong2*)(h1t + (i+j)*20 + eq*4);
                ulonglong2 rr = *(const ulonglong2*)(r1t + (i+j)*20 + eq*4);
                float wts[4] = {wt.x, wt.y, wt.z, wt.w};
                float wrs[4] = {wr.x, wr.y, wr.z, wr.w};
                #pragma unroll
                for (int kv = 0; kv < 4; kv++) {
                    u64 w2 = pk(wts[kv], wts[kv]);
                    fma2(att[kv][0], hh.x, w2);
                    fma2(att[kv][1], hh.y, w2);
                }
                #pragma unroll
                for (int kv = 0; kv < 4; kv++) {
                    u64 w3 = pk(wrs[kv], wrs[kv]);
                    fma2(arr[kv][0], rr.x, w3);
                    fma2(arr[kv][1], rr.y, w3);
                }
            }
        }
        #pragma unroll
        for (int kv = 0; kv < 4; kv++) {
            float b2 = bs2[kvg*4+kv], c2 = br2[kvg*4+kv];
            #pragma unroll
            for (int p = 0; p < 2; p++) {
                float2 t = up(att[kv][p]), r = up(arr[kv][p]);
                *(u64*)(tpwT + (kvg*4+kv)*20 + eq*4 + p*2) =
                    pk((t.x + b2) * (r.x + c2), (t.y + b2) * (r.y + c2));
            }
        }
    }
    __syncthreads();

    // ---- Phase 4a: out_v gated -> Vt[u][3c x 16e] ----
    for (int idx = tid; idx < TE * TPV; idx += BT) {
        int e = idx & 15, u = idx >> 4;
        float vx, vy, vz;
        if (u < 64) {
            float coef = tpwT[(64+u)*20+e] * spsT[u*16+e];
            vx = coef * vpsT[(192 +       u)*16+e];
            vy = coef * vpsT[(192 + 64  + u)*16+e];
            vz = coef * vpsT[(192 + 128 + u)*16+e];
        } else if (u < 128) {
            int uu = u - 64;
            float coef = tpwT[(128+uu)*20+e] * spsT[(64+uu)*16+e];
            vx = coef * vpsT[(      uu)*16+e];
            vy = coef * vpsT[( 64 + uu)*16+e];
            vz = coef * vpsT[(128 + uu)*16+e];
        } else {
            int uu = u - 128;
            float w5 = tpwT[(256+uu)*20+e] * INV_SQRT2;
            float ax = vpsT[uu*16+e],       ay = vpsT[(64+uu)*16+e],  az = vpsT[(128+uu)*16+e];
            float bx = vpsT[(192+uu)*16+e], by = vpsT[(256+uu)*16+e], bz = vpsT[(320+uu)*16+e];
            vx = w5 * (ay*bz - az*by);
            vy = w5 * (az*bx - ax*bz);
            vz = w5 * (ax*by - ay*bx);
        }
        float nrm = sqrtf(vx*vx + vy*vy + vz*vz + 1e-12f);
        float g = siluf(nrm * gwp[u] + gbp[u]);
        Vt[u*48 +  0 + e] = vx * g;
        Vt[u*48 + 16 + e] = vy * g;
        Vt[u*48 + 32 + e] = vz * g;
    }

    // ---- Phase 4b: out_s -> outsT[j][e] ----
    for (int idx = tid; idx < TE * TPS; idx += BT) {
        int e = idx & 15, j = idx >> 4;
        float val;
        if (j < 64) {
            val = tpwT[j*20+e] * spsT[j*16+e] * spsT[(64+j)*16+e];
        } else {
            int u = j - 64;
            float dt = vpsT[u*16+e]       * vpsT[(192+u)*16+e]
                     + vpsT[(64+u)*16+e]  * vpsT[(256+u)*16+e]
                     + vpsT[(128+u)*16+e] * vpsT[(320+u)*16+e];
            val = tpwT[(192+u)*20+e] * dt * INV_SQRT3;
        }
        outsT[j*16+e] = siluf(val);
    }
    __syncthreads();

    // ---- Phase 5: tid<192 -> fij_v (4v x 4cols); tid>=192 -> fij_s (2v x 4e) ----
    if (tid < 192) {
        const int vg = tid & 15;    // v = vg*4..+3
        const int cg = tid >> 4;    // cols cg*4..+3 of 48
        u64 acc[4][2];
        #pragma unroll
        for (int p = 0; p < 4; p++) acc[p][0] = acc[p][1] = pk(0.f, 0.f);
        for (int u = 0; u < TPV; u += 2) {
            #pragma unroll
            for (int j = 0; j < 2; j++) {
                float4 w = *(const float4*)(Wpost_v + (u+j)*NV + vg*4);
                ulonglong2 vv = *(const ulonglong2*)(Vt + (u+j)*48 + cg*4);
                float ws[4] = {w.x, w.y, w.z, w.w};
                #pragma unroll
                for (int p = 0; p < 4; p++) {
                    u64 ww = pk(ws[p], ws[p]);
                    fma2(acc[p][0], vv.x, ww);
                    fma2(acc[p][1], vv.y, ww);
                }
            }
        }
        const int c  = cg >> 2;            // all 4 cols share c
        const int eb = (cg & 3) * 4;       // edge base
        #pragma unroll
        for (int p = 0; p < 4; p++) {
            int v = vg*4 + p;
            #pragma unroll
            for (int h = 0; h < 2; h++) {
                float2 q = up(acc[p][h]);
                size_t o0 = (size_t)(e0 + eb + h*2)     * 256 + 64 + (size_t)v*3 + c;
                size_t o1 = (size_t)(e0 + eb + h*2 + 1) * 256 + 64 + (size_t)v*3 + c;
                out[o0] = fij_in[o0] + q.x;
                out[o1] = fij_in[o1] + q.y;
            }
        }
    } else {
        const int t  = tid - 192;   // 0..127
        const int vp = t >> 2;      // v = vp*2, vp*2+1
        const int eq = t & 3;       // edges eq*4..+3
        u64 a0[2] = {pk(0.f,0.f), pk(0.f,0.f)};
        u64 a1[2] = {pk(0.f,0.f), pk(0.f,0.f)};
        for (int j = 0; j < TPS; j += 2) {
            #pragma unroll
            for (int jj = 0; jj < 2; jj++) {
                float2 w = *(const float2*)(Wpost_s + (j+jj)*NS + vp*2);
                ulonglong2 oo = *(const ulonglong2*)(outsT + (j+jj)*16 + eq*4);
                u64 w0 = pk(w.x,w.x), w1 = pk(w.y,w.y);
                fma2(a0[0], oo.x, w0); fma2(a0[1], oo.y, w0);
                fma2(a1[0], oo.x, w1); fma2(a1[1], oo.y, w1);
            }
        }
        #pragma unroll
        for (int vv = 0; vv < 2; vv++) {
            #pragma unroll
            for (int h = 0; h < 2; h++) {
                float2 q = up(vv ? a1[h] : a0[h]);
                size_t o0 = (size_t)(e0 + eq*4 + h*2)     * 256 + vp*2 + vv;
                size_t o1 = (size_t)(e0 + eq*4 + h*2 + 1) * 256 + vp*2 + vv;
                out[o0] = fij_in[o0] + q.x;
                out[o1] = fij_in[o1] + q.y;
            }
        }
    }
}

// ---------------------------------------------------------------------------
extern "C" void kernel_launch(void* const* d_in, const int* in_sizes, int n_in,
                              void* d_out, int out_size)
{
    const float* x         = (const float*)d_in[0];
    const float* edge_attr = (const float*)d_in[1];
    const float* fij_in    = (const float*)d_in[2];
    const float* W_pre_s   = (const float*)d_in[3];
    const float* b_pre_s   = (const float*)d_in[4];
    const float* W_pre_v   = (const float*)d_in[5];
    const float* gw_pre    = (const float*)d_in[6];
    const float* gb_pre    = (const float*)d_in[7];
    const float* Ws1       = (const float*)d_in[8];
    const float* bs1       = (const float*)d_in[9];
    const float* Ws2       = (const float*)d_in[10];
    const float* bs2       = (const float*)d_in[11];
    const float* Wr1       = (const float*)d_in[12];
    const float* br1       = (const float*)d_in[13];
    const float* Wr2       = (const float*)d_in[14];
    const float* br2       = (const float*)d_in[15];
    const float* gw_post   = (const float*)d_in[16];
    const float* gb_post   = (const float*)d_in[17];
    const float* W_post_s  = (const float*)d_in[18];
    const float* W_post_v  = (const float*)d_in[19];
    const int*   ei        = (const int*)d_in[20];

    const int N = in_sizes[0] / 256;
    const int E = in_sizes[2] / 256;

    node_kernel<<<(N + 3) / 4, 256>>>(x, W_pre_s, b_pre_s, W_pre_v, gw_pre, gb_pre, N);

    const size_t shm = (size_t)SMEM_FLOATS * 4;   // 104832 B
    cudaFuncSetAttribute(edge_kernel, cudaFuncAttributeMaxDynamicSharedMemorySize, (int)shm);

    edge_kernel<<<E / TE, BT, shm>>>(
        x, edge_attr, fij_in,
        Ws1, bs1, Ws2, bs2, Wr1, br1, Wr2, br2,
        gw_post, gb_post, W_post_s, W_post_v,
        ei, (float*)d_out, E);
}